// round 14
// baseline (speedup 1.0000x reference)
#include <cuda_runtime.h>
#include <cuda_bf16.h>

// Problem constants
#define QN 256   // states
#define SN 128   // symbols
#define BN 1024  // batch
#define TN 128   // timesteps
#define NTHREADS 512

// Device scratch (allocation-free rule: static __device__ globals)
__device__ unsigned g_Pbf[SN * QN * QN / 2];     // bf16x2 exp(A), [s][q][q'] : 16 MB
__device__ uint4    g_alpha[2][BN * QN / 8];     // ping-pong bf16 alphas (512B/row)
__device__ int      g_order[TN * BN];            // per-t rows grouped by (stream,symbol)
__device__ int2     g_bkt[TN * 2 * SN];          // per (t, stream*SN+s): {start, cnt}
__device__ __align__(128) unsigned g_barA[32];   // stream-A barrier counter (padded line)
__device__ __align__(128) unsigned g_barB[32];   // stream-B barrier counter

// Dynamic SMEM layout (bytes)
#define A_ROW   528                       // 512B row + 16B pad (conflict-free LDS.32)
#define A_OFF   0                         // 32 staged alpha rows (shared A/B phases)
#define P_OFF   (32 * A_ROW)              // 16896 (P staging, startup only)
#define P_ROW   528
#define SB_OFF  (P_OFF + 256 * P_ROW)     // 152064 ; 4 bucket lists (A0,A1,B0,B1)
#define SH_BYTES (SB_OFF + 8192)          // 160256 (dynamic, opt-in; 1 CTA/SM)

// ---------------------------------------------------------------------------
__device__ __forceinline__ unsigned f22bf(float lo, float hi) {
    unsigned r;
    asm("cvt.rn.bf16x2.f32 %0, %1, %2;" : "=r"(r) : "f"(hi), "f"(lo));  // {hi,lo}
    return r;
}
__device__ __forceinline__ void ldmBT(unsigned b[4], unsigned addr) {
    asm volatile("ldmatrix.sync.aligned.m8n8.x4.trans.shared.b16 {%0,%1,%2,%3}, [%4];"
                 : "=r"(b[0]), "=r"(b[1]), "=r"(b[2]), "=r"(b[3]) : "r"(addr));
}
__device__ __forceinline__ void mma16816(float d[4], const unsigned a[4],
                                         unsigned b0, unsigned b1) {
    asm volatile("mma.sync.aligned.m16n8k16.row.col.f32.bf16.bf16.f32 "
                 "{%0,%1,%2,%3},{%4,%5,%6,%7},{%8,%9},{%0,%1,%2,%3};"
                 : "+f"(d[0]), "+f"(d[1]), "+f"(d[2]), "+f"(d[3])
                 : "r"(a[0]), "r"(a[1]), "r"(a[2]), "r"(a[3]), "r"(b0), "r"(b1));
}
__device__ __forceinline__ void cpasync16(unsigned saddr, const void* g) {
    asm volatile("cp.async.cg.shared.global [%0], [%1], 16;" :: "r"(saddr), "l"(g));
}
__device__ __forceinline__ void bar_arrive(unsigned* c) {
    asm volatile("red.release.gpu.global.add.u32 [%0], 1;" :: "l"(c) : "memory");
}
__device__ __forceinline__ void bar_wait(const unsigned* c, unsigned tgt) {
    unsigned v;
    do {
        asm volatile("ld.acquire.gpu.u32 %0, [%1];" : "=r"(v) : "l"(c));
    } while (v < tgt);
}

// ---------------------------------------------------------------------------
// P_bf16[s][q][q'] = bf16(exp(A[q][s][q'])), packed as bf16x2 (q' pairs)
__global__ void exp_kernel(const float* __restrict__ A) {
    int i = blockIdx.x * 256 + threadIdx.x;   // one thread per q'-pair
    int j2 = i & 127;
    int q = (i >> 7) & 255;
    int s = i >> 15;
    float2 v = *(const float2*)(A + (q << 15) + (s << 8) + 2 * j2);
    g_Pbf[(s << 15) + (q << 7) + j2] = f22bf(__expf(v.x), __expf(v.y));
}

// ---------------------------------------------------------------------------
// alpha_0 (bf16, linear space) in buffer 0.
__global__ void init_kernel(const float* __restrict__ init) {
    int b = blockIdx.x;
    int q = threadIdx.x;
    float iv = init[q];
    ((__nv_bfloat16*)g_alpha[0])[b * QN + q] =
        __float2bfloat16((iv > 0.0f) ? iv : 0.0f);
}

// ---------------------------------------------------------------------------
// Per-timestep bucketing by key = stream*SN + symbol (stream = b>=512).
// Also resets both barrier counters (stream-ordered before fsa_kernel).
__global__ void bucket_kernel(const int* __restrict__ xs) {
    int t = blockIdx.x;
    int tid = threadIdx.x;
    if (t == 0 && tid == 0) { g_barA[0] = 0u; g_barB[0] = 0u; }
    __shared__ int cnt[2 * SN];
    __shared__ int seg[2 * SN];
    __shared__ int off[2 * SN];
    cnt[tid] = 0;
    __syncthreads();
    for (int b = tid; b < BN; b += 256)
        atomicAdd(&cnt[(b >> 9) * SN + xs[b * TN + t]], 1);
    __syncthreads();
    if (tid == 0) {
        int acc = 0;
        for (int k = 0; k < 2 * SN; k++) { seg[k] = acc; off[k] = acc; acc += cnt[k]; }
    }
    __syncthreads();
    for (int b = tid; b < BN; b += 256) {
        int k = (b >> 9) * SN + xs[b * TN + t];
        int pos = atomicAdd(&off[k], 1);
        g_order[t * BN + pos] = b;
    }
    __syncthreads();
    g_bkt[t * 2 * SN + tid] = make_int2(seg[tid], cnt[tid]);
}

// ---------------------------------------------------------------------------
// One 16-row tile: D^T = P^T x alpha (register A-frags). mg<=8 runs only the
// group-0 chains (rows 8-15 are padding). Zero-padded staging keeps the
// unconditional MMA math safe; store guards by mg. Per-row sums identical to
// prior rounds (same chain split) -> bit-identical results.
__device__ __forceinline__ void compute_tile(
    const unsigned (&pa)[16][4], const unsigned* browB, int mg,
    const int* sbrow, __nv_bfloat16* __restrict__ pout,
    int n, int qp, float sc)
{
    const unsigned* browB1 = browB + 8 * (A_ROW / 4);
    float d0[4] = {0.f, 0.f, 0.f, 0.f}, e0[4] = {0.f, 0.f, 0.f, 0.f};
    if (mg > 8) {
        float d1[4] = {0.f, 0.f, 0.f, 0.f}, e1[4] = {0.f, 0.f, 0.f, 0.f};
        #pragma unroll
        for (int k16 = 0; k16 < 16; k16 += 2) {
            mma16816(d0, pa[k16],     browB[k16 * 8],        browB[k16 * 8 + 4]);
            mma16816(d1, pa[k16],     browB1[k16 * 8],       browB1[k16 * 8 + 4]);
            mma16816(e0, pa[k16 + 1], browB[(k16 + 1) * 8],  browB[(k16 + 1) * 8 + 4]);
            mma16816(e1, pa[k16 + 1], browB1[(k16 + 1) * 8], browB1[(k16 + 1) * 8 + 4]);
        }
        #pragma unroll
        for (int r = 0; r < 4; r++) { d0[r] += e0[r]; d1[r] += e1[r]; }
        if (8 + n < mg) {
            __nv_bfloat16* r0 = pout + sbrow[8 + n] * QN + qp;
            r0[0] = __float2bfloat16(d1[0] * sc);
            r0[8] = __float2bfloat16(d1[2] * sc);
        }
        if (9 + n < mg) {
            __nv_bfloat16* r1 = pout + sbrow[9 + n] * QN + qp;
            r1[0] = __float2bfloat16(d1[1] * sc);
            r1[8] = __float2bfloat16(d1[3] * sc);
        }
    } else {
        #pragma unroll
        for (int k16 = 0; k16 < 16; k16 += 2) {
            mma16816(d0, pa[k16],     browB[k16 * 8],       browB[k16 * 8 + 4]);
            mma16816(e0, pa[k16 + 1], browB[(k16 + 1) * 8], browB[(k16 + 1) * 8 + 4]);
        }
        #pragma unroll
        for (int r = 0; r < 4; r++) d0[r] += e0[r];
    }
    if (n < mg) {
        __nv_bfloat16* r0 = pout + sbrow[n] * QN + qp;
        r0[0] = __float2bfloat16(d0[0] * sc);
        r0[8] = __float2bfloat16(d0[2] * sc);
    }
    if (n + 1 < mg) {
        __nv_bfloat16* r1 = pout + sbrow[n + 1] * QN + qp;
        r1[0] = __float2bfloat16(d0[1] * sc);
        r1[8] = __float2bfloat16(d0[3] * sc);
    }
}

// ---------------------------------------------------------------------------
// Persistent FSA kernel, dual-stream pipelined: batch split b<512 / b>=512
// (independent chains). Per step: compute A, arrive barA, compute B, arrive
// barB; the wait for each stream's barrier is separated from its arrive by
// the other stream's compute, hiding barrier latency + skew. P^T A-frags in
// registers (extracted once); t+1 bucket lists prefetched in the MMA shadow.
__global__ void __launch_bounds__(NTHREADS, 1) fsa_kernel() {
    extern __shared__ __align__(16) unsigned char sh[];
    unsigned shb = (unsigned)__cvta_generic_to_shared(sh);
    const int s = blockIdx.x;
    const int tid = threadIdx.x, w = tid >> 5, lane = tid & 31;
    int* sbA0 = (int*)(sh + SB_OFF);
    int* sbA1 = sbA0 + 512;
    int* sbB0 = sbA0 + 1024;
    int* sbB1 = sbA0 + 1536;

    // ---- stage P[s] (256 rows x 512B) into SMEM (startup only)
    {
        const char* gP = (const char*)g_Pbf + ((size_t)s << 17);
        for (int i = tid; i < 256 * 32; i += NTHREADS) {
            int r = i >> 5, c = i & 31;
            cpasync16(shb + P_OFF + r * P_ROW + c * 16, gP + (size_t)r * 512 + c * 16);
        }
        asm volatile("cp.async.commit_group;");
        asm volatile("cp.async.wait_group 0;");
        __syncthreads();
    }

    // ---- extract P^T A-fragments into registers (verified addressing)
    unsigned pa[16][4];
    {
        const unsigned aP = shb + P_OFF
            + ((lane & 7) + ((lane >> 4) & 1) * 8) * P_ROW
            + (w * 16 + ((lane >> 3) & 1) * 8) * 2;
        #pragma unroll
        for (int k16 = 0; k16 < 16; k16++)
            ldmBT(pa[k16], aP + k16 * 16 * P_ROW);
    }

    // ---- prefetch step 0 buckets
    int2 bktA = g_bkt[s];
    int2 bktB = g_bkt[SN + s];
    for (int i = tid; i < bktA.y; i += NTHREADS) sbA0[i] = g_order[bktA.x + i];
    for (int i = tid; i < bktB.y; i += NTHREADS) sbB0[i] = g_order[bktB.x + i];
    __syncthreads();

    const float sc = 0.00390625f;   // 2^-8 exact per-step renorm (at epilogue)
    const unsigned* browB =
        (const unsigned*)(sh + A_OFF + (lane >> 2) * A_ROW) + (lane & 3);
    const int n = 2 * (lane & 3);           // D^T frag batch-col pair
    const int qp = w * 16 + (lane >> 2);    // D^T frag q' row (and +8)

    // one stream-phase: stage (zero-pad), shadow-prefetch next list, GEMM, epi
    auto phase = [&](int2 bkt, const int* sbc, int* sbn, int2 bktn, int nbase,
                     const __nv_bfloat16* pin, __nv_bfloat16* pout) {
        const int cnt = bkt.y;
        bool pf = (nbase >= 0);
        int o = 0;
        while (o < cnt) {
            const int mg = min(cnt - o, 32);
            const int rmax = (mg <= 16) ? 16 : 32;
            for (int r = w; r < rmax; r += 16) {
                uint4 pk = make_uint4(0, 0, 0, 0);
                if (r < mg)
                    pk = __ldcg((const uint4*)(pin + sbc[o + r] * QN) + lane);
                *(uint4*)(sh + A_OFF + r * A_ROW + lane * 16) = pk;
            }
            __syncthreads();
            if (pf) {   // t+1 row list in the MMA shadow
                for (int i = tid; i < bktn.y; i += NTHREADS)
                    sbn[i] = g_order[nbase + bktn.x + i];
                pf = false;
            }
            compute_tile(pa, browB, min(mg, 16), sbc + o, pout, n, qp, sc);
            if (mg > 16)
                compute_tile(pa, browB + 16 * (A_ROW / 4), mg - 16,
                             sbc + o + 16, pout, n, qp, sc);
            __syncthreads();   // epilogue stores + sbn prefetch complete
            o += 32;
        }
        if (pf)   // empty bucket: still prefetch (next sync orders the stores)
            for (int i = tid; i < bktn.y; i += NTHREADS)
                sbn[i] = g_order[nbase + bktn.x + i];
    };

    for (int t = 0; t < TN; t++) {
        const __nv_bfloat16* __restrict__ pin = (const __nv_bfloat16*)g_alpha[t & 1];
        __nv_bfloat16* __restrict__ pout = (__nv_bfloat16*)g_alpha[(t & 1) ^ 1];
        int* sbcA = (t & 1) ? sbA1 : sbA0;
        int* sbnA = (t & 1) ? sbA0 : sbA1;
        int* sbcB = (t & 1) ? sbB1 : sbB0;
        int* sbnB = (t & 1) ? sbB0 : sbB1;
        const int nbase = (t + 1 < TN) ? (t + 1) * BN : -1;
        int2 bktAn = make_int2(0, 0), bktBn = make_int2(0, 0);
        if (t + 1 < TN) {
            bktAn = g_bkt[(t + 1) * 2 * SN + s];
            bktBn = g_bkt[(t + 1) * 2 * SN + SN + s];
        }

        // ---- stream A: wait (hidden behind prev step's B compute), compute, arrive
        if (t > 0) {
            if (tid == 0) bar_wait(g_barA, (unsigned)t * SN);
            __syncthreads();
        }
        phase(bktA, sbcA, sbnA, bktAn, nbase, pin, pout);
        if (t + 1 < TN && tid == 0) bar_arrive(g_barA);

        // ---- stream B: wait (hidden behind this step's A compute), compute, arrive
        if (t > 0) {
            if (tid == 0) bar_wait(g_barB, (unsigned)t * SN);
            __syncthreads();
        }
        phase(bktB, sbcB, sbnB, bktBn, nbase, pin, pout);
        if (t + 1 < TN && tid == 0) bar_arrive(g_barB);

        bktA = bktAn;
        bktB = bktBn;
    }
}

// ---------------------------------------------------------------------------
// out[b] = log( sum_q alpha_bf16[b][q] * exp(final[q]) ) + 128*ln(256)
__global__ void final_kernel(const float* __restrict__ finalw, float* __restrict__ out) {
    int b = blockIdx.x * 8 + (threadIdx.x >> 5);
    int lane = threadIdx.x & 31;
    const __nv_bfloat16* ar = (const __nv_bfloat16*)g_alpha[0] + b * QN;  // T even
    float sum = 0.0f;
    #pragma unroll
    for (int i = 0; i < 8; i++) {
        int q = lane + 32 * i;
        sum += __bfloat162float(ar[q]) * __expf(finalw[q]);
    }
    #pragma unroll
    for (int o = 16; o > 0; o >>= 1) sum += __shfl_xor_sync(0xFFFFFFFFu, sum, o);
    if (lane == 0)
        out[b] = logf(sum) + (float)(128.0 * 5.545177444479562);  // T * ln(256)
}

// ---------------------------------------------------------------------------
extern "C" void kernel_launch(void* const* d_in, const int* in_sizes, int n_in,
                              void* d_out, int out_size) {
    const float* A      = (const float*)d_in[0];  // [Q,S,Q] fp32
    const float* init   = (const float*)d_in[1];  // [Q]
    const float* finalw = (const float*)d_in[2];  // [Q]
    const int*   xs     = (const int*)d_in[3];    // [B,T] int32
    float* out = (float*)d_out;                   // [B]

    cudaFuncSetAttribute(fsa_kernel,
                         cudaFuncAttributeMaxDynamicSharedMemorySize, SH_BYTES);

    exp_kernel<<<(SN * QN * QN / 2) / 256, 256>>>(A);
    init_kernel<<<BN, QN>>>(init);
    bucket_kernel<<<TN, 256>>>(xs);
    fsa_kernel<<<SN, NTHREADS, SH_BYTES>>>();
    final_kernel<<<BN / 8, 256>>>(finalw, out);
}

// round 15
// speedup vs baseline: 1.3237x; 1.3237x over previous
#include <cuda_runtime.h>
#include <cuda_bf16.h>

// Problem constants
#define QN 256   // states
#define SN 128   // symbols
#define BN 1024  // batch
#define TN 128   // timesteps
#define NTHREADS 512

// Device scratch (allocation-free rule: static __device__ globals)
__device__ unsigned g_Pbf[SN * QN * QN / 2];     // bf16x2 exp(A), [s][q][q'] : 16 MB
__device__ uint4    g_alpha[2][BN * QN / 8];     // ping-pong bf16 alphas (512B/row)
__device__ int      g_order[TN * BN];            // per-t packed {prod<<16 | row}
__device__ int2     g_bkt[TN * SN];              // per (t,s): {start, cnt}
__device__ unsigned g_done[SN * 32];             // per-CTA step counters (own line each)

// Dynamic SMEM layout (bytes)
#define A_ROW   528                       // 512B row + 16B pad (conflict-free LDS.32)
#define A_OFF   0                         // 32 staged alpha rows
#define P_OFF   (32 * A_ROW)              // 16896 (P staging, startup only)
#define P_ROW   528
#define SB_OFF  (P_OFF + 256 * P_ROW)     // 152064 ; double-buffered bucket lists
#define SH_BYTES (SB_OFF + 4096)          // 156160 (dynamic, opt-in; 1 CTA/SM)

// ---------------------------------------------------------------------------
__device__ __forceinline__ unsigned f22bf(float lo, float hi) {
    unsigned r;
    asm("cvt.rn.bf16x2.f32 %0, %1, %2;" : "=r"(r) : "f"(hi), "f"(lo));  // {hi,lo}
    return r;
}
__device__ __forceinline__ void ldmBT(unsigned b[4], unsigned addr) {
    asm volatile("ldmatrix.sync.aligned.m8n8.x4.trans.shared.b16 {%0,%1,%2,%3}, [%4];"
                 : "=r"(b[0]), "=r"(b[1]), "=r"(b[2]), "=r"(b[3]) : "r"(addr));
}
__device__ __forceinline__ void mma16816(float d[4], const unsigned a[4],
                                         unsigned b0, unsigned b1) {
    asm volatile("mma.sync.aligned.m16n8k16.row.col.f32.bf16.bf16.f32 "
                 "{%0,%1,%2,%3},{%4,%5,%6,%7},{%8,%9},{%0,%1,%2,%3};"
                 : "+f"(d[0]), "+f"(d[1]), "+f"(d[2]), "+f"(d[3])
                 : "r"(a[0]), "r"(a[1]), "r"(a[2]), "r"(a[3]), "r"(b0), "r"(b1));
}
__device__ __forceinline__ void cpasync16(unsigned saddr, const void* g) {
    asm volatile("cp.async.cg.shared.global [%0], [%1], 16;" :: "r"(saddr), "l"(g));
}

// ---------------------------------------------------------------------------
// P_bf16[s][q][q'] = bf16(exp(A[q][s][q'])), packed as bf16x2 (q' pairs)
__global__ void exp_kernel(const float* __restrict__ A) {
    int i = blockIdx.x * 256 + threadIdx.x;   // one thread per q'-pair
    int j2 = i & 127;
    int q = (i >> 7) & 255;
    int s = i >> 15;
    float2 v = *(const float2*)(A + (q << 15) + (s << 8) + 2 * j2);
    g_Pbf[(s << 15) + (q << 7) + j2] = f22bf(__expf(v.x), __expf(v.y));
}

// ---------------------------------------------------------------------------
// alpha_0 (bf16, linear space) in buffer 0.
__global__ void init_kernel(const float* __restrict__ init) {
    int b = blockIdx.x;
    int q = threadIdx.x;
    float iv = init[q];
    ((__nv_bfloat16*)g_alpha[0])[b * QN + q] =
        __float2bfloat16((iv > 0.0f) ? iv : 0.0f);
}

// ---------------------------------------------------------------------------
// Per-timestep bucketing. Order entries pack {producer CTA at t-1} << 16 | row.
// Block t also resets g_done[t] (stream-ordered before fsa_kernel).
__global__ void bucket_kernel(const int* __restrict__ xs) {
    int t = blockIdx.x;
    int tid = threadIdx.x;
    if (tid == 0) g_done[t * 32] = 0u;      // t ranges over [0,128) == s range
    __shared__ int cnt[SN];
    __shared__ int seg[SN];
    __shared__ int off[SN];
    if (tid < SN) cnt[tid] = 0;
    __syncthreads();
    for (int b = tid; b < BN; b += 256)
        atomicAdd(&cnt[xs[b * TN + t]], 1);
    __syncthreads();
    if (tid == 0) {
        int acc = 0;
        for (int s = 0; s < SN; s++) { seg[s] = acc; off[s] = acc; acc += cnt[s]; }
    }
    __syncthreads();
    for (int b = tid; b < BN; b += 256) {
        int s = xs[b * TN + t];
        int pos = atomicAdd(&off[s], 1);
        int prod = (t > 0) ? xs[b * TN + t - 1] : 0;
        g_order[t * BN + pos] = b | (prod << 16);
    }
    __syncthreads();
    if (tid < SN)
        g_bkt[t * SN + tid] = make_int2(seg[tid], cnt[tid]);
}

// ---------------------------------------------------------------------------
// One 16-row tile: D^T = P^T x alpha (register A-frags). Entries in sbrow are
// packed {prod<<16 | row}; mask to get the row. mg<=8 runs only group-0 chains.
__device__ __forceinline__ void compute_tile(
    const unsigned (&pa)[16][4], const unsigned* browB, int mg,
    const int* sbrow, __nv_bfloat16* __restrict__ pout,
    int n, int qp, float sc)
{
    const unsigned* browB1 = browB + 8 * (A_ROW / 4);
    float d0[4] = {0.f, 0.f, 0.f, 0.f}, e0[4] = {0.f, 0.f, 0.f, 0.f};
    if (mg > 8) {
        float d1[4] = {0.f, 0.f, 0.f, 0.f}, e1[4] = {0.f, 0.f, 0.f, 0.f};
        #pragma unroll
        for (int k16 = 0; k16 < 16; k16 += 2) {
            mma16816(d0, pa[k16],     browB[k16 * 8],        browB[k16 * 8 + 4]);
            mma16816(d1, pa[k16],     browB1[k16 * 8],       browB1[k16 * 8 + 4]);
            mma16816(e0, pa[k16 + 1], browB[(k16 + 1) * 8],  browB[(k16 + 1) * 8 + 4]);
            mma16816(e1, pa[k16 + 1], browB1[(k16 + 1) * 8], browB1[(k16 + 1) * 8 + 4]);
        }
        #pragma unroll
        for (int r = 0; r < 4; r++) { d0[r] += e0[r]; d1[r] += e1[r]; }
        if (8 + n < mg) {
            __nv_bfloat16* r0 = pout + (sbrow[8 + n] & 0xFFFF) * QN + qp;
            r0[0] = __float2bfloat16(d1[0] * sc);
            r0[8] = __float2bfloat16(d1[2] * sc);
        }
        if (9 + n < mg) {
            __nv_bfloat16* r1 = pout + (sbrow[9 + n] & 0xFFFF) * QN + qp;
            r1[0] = __float2bfloat16(d1[1] * sc);
            r1[8] = __float2bfloat16(d1[3] * sc);
        }
    } else {
        #pragma unroll
        for (int k16 = 0; k16 < 16; k16 += 2) {
            mma16816(d0, pa[k16],     browB[k16 * 8],       browB[k16 * 8 + 4]);
            mma16816(e0, pa[k16 + 1], browB[(k16 + 1) * 8], browB[(k16 + 1) * 8 + 4]);
        }
        #pragma unroll
        for (int r = 0; r < 4; r++) d0[r] += e0[r];
    }
    if (n < mg) {
        __nv_bfloat16* r0 = pout + (sbrow[n] & 0xFFFF) * QN + qp;
        r0[0] = __float2bfloat16(d0[0] * sc);
        r0[8] = __float2bfloat16(d0[2] * sc);
    }
    if (n + 1 < mg) {
        __nv_bfloat16* r1 = pout + (sbrow[n + 1] & 0xFFFF) * QN + qp;
        r1[0] = __float2bfloat16(d0[1] * sc);
        r1[8] = __float2bfloat16(d0[3] * sc);
    }
}

// ---------------------------------------------------------------------------
// Persistent FSA kernel, dataflow-synchronized: CTA s at step t waits ONLY for
// the <=cnt producer CTAs of its bucket rows (lane-parallel acquire poll on
// per-CTA done counters), not a global barrier. Each CTA publishes its own
// counter with one st.release per step (no atomics, no fan-in). Row-chained
// ordering makes the 2-buffer ping-pong WAR-safe for arbitrary CTA drift.
__global__ void __launch_bounds__(NTHREADS, 1) fsa_kernel() {
    extern __shared__ __align__(16) unsigned char sh[];
    unsigned shb = (unsigned)__cvta_generic_to_shared(sh);
    const int s = blockIdx.x;
    const int tid = threadIdx.x, w = tid >> 5, lane = tid & 31;
    int* sbuf0 = (int*)(sh + SB_OFF);
    int* sbuf1 = sbuf0 + 512;

    // ---- stage P[s] (256 rows x 512B) into SMEM (startup only)
    {
        const char* gP = (const char*)g_Pbf + ((size_t)s << 17);
        for (int i = tid; i < 256 * 32; i += NTHREADS) {
            int r = i >> 5, c = i & 31;
            cpasync16(shb + P_OFF + r * P_ROW + c * 16, gP + (size_t)r * 512 + c * 16);
        }
        asm volatile("cp.async.commit_group;");
        asm volatile("cp.async.wait_group 0;");
        __syncthreads();
    }

    // ---- extract P^T A-fragments into registers (verified addressing)
    unsigned pa[16][4];
    {
        const unsigned aP = shb + P_OFF
            + ((lane & 7) + ((lane >> 4) & 1) * 8) * P_ROW
            + (w * 16 + ((lane >> 3) & 1) * 8) * 2;
        #pragma unroll
        for (int k16 = 0; k16 < 16; k16++)
            ldmBT(pa[k16], aP + k16 * 16 * P_ROW);
    }

    // ---- prefetch step 0 bucket into sbuf0
    int2 bkt = g_bkt[s];
    for (int i = tid; i < bkt.y; i += NTHREADS)
        sbuf0[i] = g_order[bkt.x + i];
    __syncthreads();

    const float sc = 0.00390625f;   // 2^-8 exact per-step renorm (at epilogue)
    const unsigned* browB =
        (const unsigned*)(sh + A_OFF + (lane >> 2) * A_ROW) + (lane & 3);
    const int n = 2 * (lane & 3);           // D^T frag batch-col pair
    const int qp = w * 16 + (lane >> 2);    // D^T frag q' row (and +8)

    for (int t = 0; t < TN; t++) {
        const __nv_bfloat16* __restrict__ pin = (const __nv_bfloat16*)g_alpha[t & 1];
        __nv_bfloat16* __restrict__ pout = (__nv_bfloat16*)g_alpha[(t & 1) ^ 1];
        int* sbc = (t & 1) ? sbuf1 : sbuf0;
        int* sbn = (t & 1) ? sbuf0 : sbuf1;
        const int cnt = bkt.y;

        // t+1 bucket bounds: independent LDG, issued before the wait
        int2 bktn = make_int2(0, 0);
        if (t + 1 < TN) bktn = g_bkt[(t + 1) * SN + s];

        // ---- dataflow wait: producers of this bucket must be at step >= t
        if (t > 0 && w == 0) {
            for (int i = lane; i < cnt; i += 32) {
                const unsigned* c = &g_done[(unsigned)(sbc[i] >> 16) * 32];
                unsigned v;
                do {
                    asm volatile("ld.acquire.gpu.u32 %0, [%1];" : "=r"(v) : "l"(c));
                } while (v < (unsigned)t);
            }
        }
        __syncthreads();

        bool pf = (t + 1 < TN);
        int o = 0;
        while (o < cnt) {
            const int mg = min(cnt - o, 32);
            const int rmax = (mg <= 16) ? 16 : 32;

            // ---- stage alpha rows (bf16, zero-pad)
            for (int r = w; r < rmax; r += 16) {
                uint4 pk = make_uint4(0, 0, 0, 0);
                if (r < mg)
                    pk = __ldcg((const uint4*)(pin + (sbc[o + r] & 0xFFFF) * QN) + lane);
                *(uint4*)(sh + A_OFF + r * A_ROW + lane * 16) = pk;
            }
            __syncthreads();

            // ---- prefetch t+1 row list in the MMA shadow (once per step)
            if (pf) {
                for (int i = tid; i < bktn.y; i += NTHREADS)
                    sbn[i] = g_order[(t + 1) * BN + bktn.x + i];
                pf = false;
            }

            // ---- tile 0 (rows o..o+15)
            compute_tile(pa, browB, min(mg, 16), sbc + o, pout, n, qp, sc);
            // ---- tile 1 (rows o+16..o+31), rare straggler path
            if (mg > 16)
                compute_tile(pa, browB + 16 * (A_ROW / 4), mg - 16,
                             sbc + o + 16, pout, n, qp, sc);

            __syncthreads();   // epilogue stores + sbn prefetch complete
            o += 32;
        }
        if (pf) {   // empty bucket: still prefetch next list
            for (int i = tid; i < bktn.y; i += NTHREADS)
                sbn[i] = g_order[(t + 1) * BN + bktn.x + i];
            __syncthreads();
        }

        // ---- publish: this CTA finished step t (own line, no atomics)
        if (t + 1 < TN && tid == 0)
            asm volatile("st.release.gpu.global.u32 [%0], %1;"
                         :: "l"(&g_done[s * 32]), "r"((unsigned)(t + 1)) : "memory");
        bkt = bktn;
    }
}

// ---------------------------------------------------------------------------
// out[b] = log( sum_q alpha_bf16[b][q] * exp(final[q]) ) + 128*ln(256)
__global__ void final_kernel(const float* __restrict__ finalw, float* __restrict__ out) {
    int b = blockIdx.x * 8 + (threadIdx.x >> 5);
    int lane = threadIdx.x & 31;
    const __nv_bfloat16* ar = (const __nv_bfloat16*)g_alpha[0] + b * QN;  // T even
    float sum = 0.0f;
    #pragma unroll
    for (int i = 0; i < 8; i++) {
        int q = lane + 32 * i;
        sum += __bfloat162float(ar[q]) * __expf(finalw[q]);
    }
    #pragma unroll
    for (int o = 16; o > 0; o >>= 1) sum += __shfl_xor_sync(0xFFFFFFFFu, sum, o);
    if (lane == 0)
        out[b] = logf(sum) + (float)(128.0 * 5.545177444479562);  // T * ln(256)
}

// ---------------------------------------------------------------------------
extern "C" void kernel_launch(void* const* d_in, const int* in_sizes, int n_in,
                              void* d_out, int out_size) {
    const float* A      = (const float*)d_in[0];  // [Q,S,Q] fp32
    const float* init   = (const float*)d_in[1];  // [Q]
    const float* finalw = (const float*)d_in[2];  // [Q]
    const int*   xs     = (const int*)d_in[3];    // [B,T] int32
    float* out = (float*)d_out;                   // [B]

    cudaFuncSetAttribute(fsa_kernel,
                         cudaFuncAttributeMaxDynamicSharedMemorySize, SH_BYTES);

    exp_kernel<<<(SN * QN * QN / 2) / 256, 256>>>(A);
    init_kernel<<<BN, QN>>>(init);
    bucket_kernel<<<TN, 256>>>(xs);
    fsa_kernel<<<SN, NTHREADS, SH_BYTES>>>();
    final_kernel<<<BN / 8, 256>>>(finalw, out);
}

// round 16
// speedup vs baseline: 1.4342x; 1.0835x over previous
#include <cuda_runtime.h>
#include <cuda_bf16.h>

// Problem constants
#define QN 256   // states
#define SN 128   // symbols
#define BN 1024  // batch
#define TN 128   // timesteps
#define NTHREADS 512

// Device scratch (allocation-free rule: static __device__ globals)
__device__ unsigned g_Pbf[SN * QN * QN / 2];     // bf16x2 exp(A), [s][q][q'] : 16 MB
__device__ uint4    g_alpha[2][BN * QN / 8];     // ping-pong bf16 alphas (512B/row)
__device__ int      g_order[TN * BN];            // per-t packed {prod<<16 | row}
__device__ int2     g_bkt[TN * SN];              // per (t,s): {start, cnt}
__device__ unsigned g_done[SN * 32];             // per-CTA step counters (own line each)

// Dynamic SMEM layout (bytes)
#define A_ROW   528                       // 512B row + 16B pad (conflict-free LDS.32)
#define A_OFF   0                         // 32 staged alpha rows
#define P_OFF   (32 * A_ROW)              // 16896 (P staging, startup only)
#define P_ROW   528
#define SB_OFF  (P_OFF + 256 * P_ROW)     // 152064 ; double-buffered bucket lists
#define SH_BYTES (SB_OFF + 4096)          // 156160 (dynamic, opt-in; 1 CTA/SM)

// ---------------------------------------------------------------------------
__device__ __forceinline__ unsigned f22bf(float lo, float hi) {
    unsigned r;
    asm("cvt.rn.bf16x2.f32 %0, %1, %2;" : "=r"(r) : "f"(hi), "f"(lo));  // {hi,lo}
    return r;
}
__device__ __forceinline__ void ldmBT(unsigned b[4], unsigned addr) {
    asm volatile("ldmatrix.sync.aligned.m8n8.x4.trans.shared.b16 {%0,%1,%2,%3}, [%4];"
                 : "=r"(b[0]), "=r"(b[1]), "=r"(b[2]), "=r"(b[3]) : "r"(addr));
}
__device__ __forceinline__ void mma16816(float d[4], const unsigned a[4],
                                         unsigned b0, unsigned b1) {
    asm volatile("mma.sync.aligned.m16n8k16.row.col.f32.bf16.bf16.f32 "
                 "{%0,%1,%2,%3},{%4,%5,%6,%7},{%8,%9},{%0,%1,%2,%3};"
                 : "+f"(d[0]), "+f"(d[1]), "+f"(d[2]), "+f"(d[3])
                 : "r"(a[0]), "r"(a[1]), "r"(a[2]), "r"(a[3]), "r"(b0), "r"(b1));
}
__device__ __forceinline__ void cpasync16(unsigned saddr, const void* g) {
    asm volatile("cp.async.cg.shared.global [%0], [%1], 16;" :: "r"(saddr), "l"(g));
}

// ---------------------------------------------------------------------------
// P_bf16[s][q][q'] = bf16(exp(A[q][s][q'])), packed as bf16x2 (q' pairs)
__global__ void exp_kernel(const float* __restrict__ A) {
    int i = blockIdx.x * 256 + threadIdx.x;   // one thread per q'-pair
    int j2 = i & 127;
    int q = (i >> 7) & 255;
    int s = i >> 15;
    float2 v = *(const float2*)(A + (q << 15) + (s << 8) + 2 * j2);
    g_Pbf[(s << 15) + (q << 7) + j2] = f22bf(__expf(v.x), __expf(v.y));
}

// ---------------------------------------------------------------------------
// alpha_0 (bf16, linear space) in buffer 0.
__global__ void init_kernel(const float* __restrict__ init) {
    int b = blockIdx.x;
    int q = threadIdx.x;
    float iv = init[q];
    ((__nv_bfloat16*)g_alpha[0])[b * QN + q] =
        __float2bfloat16((iv > 0.0f) ? iv : 0.0f);
}

// ---------------------------------------------------------------------------
// Per-timestep bucketing. Order entries pack {producer CTA at t-1} << 16 | row.
// Block t also resets g_done[t] (stream-ordered before fsa_kernel).
__global__ void bucket_kernel(const int* __restrict__ xs) {
    int t = blockIdx.x;
    int tid = threadIdx.x;
    if (tid == 0) g_done[t * 32] = 0u;      // t ranges over [0,128) == s range
    __shared__ int cnt[SN];
    __shared__ int seg[SN];
    __shared__ int off[SN];
    if (tid < SN) cnt[tid] = 0;
    __syncthreads();
    for (int b = tid; b < BN; b += 256)
        atomicAdd(&cnt[xs[b * TN + t]], 1);
    __syncthreads();
    if (tid == 0) {
        int acc = 0;
        for (int s = 0; s < SN; s++) { seg[s] = acc; off[s] = acc; acc += cnt[s]; }
    }
    __syncthreads();
    for (int b = tid; b < BN; b += 256) {
        int s = xs[b * TN + t];
        int pos = atomicAdd(&off[s], 1);
        int prod = (t > 0) ? xs[b * TN + t - 1] : 0;
        g_order[t * BN + pos] = b | (prod << 16);
    }
    __syncthreads();
    if (tid < SN)
        g_bkt[t * SN + tid] = make_int2(seg[tid], cnt[tid]);
}

// ---------------------------------------------------------------------------
// One 16-row tile: D^T = P^T x alpha (register A-frags). Entries in sbrow are
// packed {prod<<16 | row}; mask to get the row. mg<=8 runs only group-0 chains.
__device__ __forceinline__ void compute_tile(
    const unsigned (&pa)[16][4], const unsigned* browB, int mg,
    const int* sbrow, __nv_bfloat16* __restrict__ pout,
    int n, int qp, float sc)
{
    const unsigned* browB1 = browB + 8 * (A_ROW / 4);
    float d0[4] = {0.f, 0.f, 0.f, 0.f}, e0[4] = {0.f, 0.f, 0.f, 0.f};
    if (mg > 8) {
        float d1[4] = {0.f, 0.f, 0.f, 0.f}, e1[4] = {0.f, 0.f, 0.f, 0.f};
        #pragma unroll
        for (int k16 = 0; k16 < 16; k16 += 2) {
            mma16816(d0, pa[k16],     browB[k16 * 8],        browB[k16 * 8 + 4]);
            mma16816(d1, pa[k16],     browB1[k16 * 8],       browB1[k16 * 8 + 4]);
            mma16816(e0, pa[k16 + 1], browB[(k16 + 1) * 8],  browB[(k16 + 1) * 8 + 4]);
            mma16816(e1, pa[k16 + 1], browB1[(k16 + 1) * 8], browB1[(k16 + 1) * 8 + 4]);
        }
        #pragma unroll
        for (int r = 0; r < 4; r++) { d0[r] += e0[r]; d1[r] += e1[r]; }
        if (8 + n < mg) {
            __nv_bfloat16* r0 = pout + (sbrow[8 + n] & 0xFFFF) * QN + qp;
            r0[0] = __float2bfloat16(d1[0] * sc);
            r0[8] = __float2bfloat16(d1[2] * sc);
        }
        if (9 + n < mg) {
            __nv_bfloat16* r1 = pout + (sbrow[9 + n] & 0xFFFF) * QN + qp;
            r1[0] = __float2bfloat16(d1[1] * sc);
            r1[8] = __float2bfloat16(d1[3] * sc);
        }
    } else {
        #pragma unroll
        for (int k16 = 0; k16 < 16; k16 += 2) {
            mma16816(d0, pa[k16],     browB[k16 * 8],       browB[k16 * 8 + 4]);
            mma16816(e0, pa[k16 + 1], browB[(k16 + 1) * 8], browB[(k16 + 1) * 8 + 4]);
        }
        #pragma unroll
        for (int r = 0; r < 4; r++) d0[r] += e0[r];
    }
    if (n < mg) {
        __nv_bfloat16* r0 = pout + (sbrow[n] & 0xFFFF) * QN + qp;
        r0[0] = __float2bfloat16(d0[0] * sc);
        r0[8] = __float2bfloat16(d0[2] * sc);
    }
    if (n + 1 < mg) {
        __nv_bfloat16* r1 = pout + (sbrow[n + 1] & 0xFFFF) * QN + qp;
        r1[0] = __float2bfloat16(d0[1] * sc);
        r1[8] = __float2bfloat16(d0[3] * sc);
    }
}

// ---------------------------------------------------------------------------
// Persistent FSA kernel, dataflow-synchronized with FUSED per-row wait+stage:
// the warp that stages row r polls row r's producer counter (all lanes
// converge on one line) and issues the row's LDG immediately on release.
// Ready rows load with zero wait; the stage sync absorbs only the late ones.
// Each CTA publishes its own done counter with one st.release per step.
__global__ void __launch_bounds__(NTHREADS, 1) fsa_kernel() {
    extern __shared__ __align__(16) unsigned char sh[];
    unsigned shb = (unsigned)__cvta_generic_to_shared(sh);
    const int s = blockIdx.x;
    const int tid = threadIdx.x, w = tid >> 5, lane = tid & 31;
    int* sbuf0 = (int*)(sh + SB_OFF);
    int* sbuf1 = sbuf0 + 512;

    // ---- stage P[s] (256 rows x 512B) into SMEM (startup only)
    {
        const char* gP = (const char*)g_Pbf + ((size_t)s << 17);
        for (int i = tid; i < 256 * 32; i += NTHREADS) {
            int r = i >> 5, c = i & 31;
            cpasync16(shb + P_OFF + r * P_ROW + c * 16, gP + (size_t)r * 512 + c * 16);
        }
        asm volatile("cp.async.commit_group;");
        asm volatile("cp.async.wait_group 0;");
        __syncthreads();
    }

    // ---- extract P^T A-fragments into registers (verified addressing)
    unsigned pa[16][4];
    {
        const unsigned aP = shb + P_OFF
            + ((lane & 7) + ((lane >> 4) & 1) * 8) * P_ROW
            + (w * 16 + ((lane >> 3) & 1) * 8) * 2;
        #pragma unroll
        for (int k16 = 0; k16 < 16; k16++)
            ldmBT(pa[k16], aP + k16 * 16 * P_ROW);
    }

    // ---- prefetch step 0 bucket into sbuf0
    int2 bkt = g_bkt[s];
    for (int i = tid; i < bkt.y; i += NTHREADS)
        sbuf0[i] = g_order[bkt.x + i];
    __syncthreads();

    const float sc = 0.00390625f;   // 2^-8 exact per-step renorm (at epilogue)
    const unsigned* browB =
        (const unsigned*)(sh + A_OFF + (lane >> 2) * A_ROW) + (lane & 3);
    const int n = 2 * (lane & 3);           // D^T frag batch-col pair
    const int qp = w * 16 + (lane >> 2);    // D^T frag q' row (and +8)

    for (int t = 0; t < TN; t++) {
        const __nv_bfloat16* __restrict__ pin = (const __nv_bfloat16*)g_alpha[t & 1];
        __nv_bfloat16* __restrict__ pout = (__nv_bfloat16*)g_alpha[(t & 1) ^ 1];
        int* sbc = (t & 1) ? sbuf1 : sbuf0;
        int* sbn = (t & 1) ? sbuf0 : sbuf1;
        const int cnt = bkt.y;

        // t+1 bucket bounds: independent LDG, issued before staging
        int2 bktn = make_int2(0, 0);
        if (t + 1 < TN) bktn = g_bkt[(t + 1) * SN + s];

        bool pf = (t + 1 < TN);
        int o = 0;
        while (o < cnt) {
            const int mg = min(cnt - o, 32);
            const int rmax = (mg <= 16) ? 16 : 32;

            // ---- fused wait+stage: warp waits on ITS row's producer, then loads
            for (int r = w; r < rmax; r += 16) {
                uint4 pk = make_uint4(0, 0, 0, 0);
                if (r < mg) {
                    int e = sbc[o + r];
                    if (t > 0) {
                        const unsigned* c = &g_done[(unsigned)(e >> 16) * 32];
                        unsigned v;
                        do {   // all lanes converge on one line (broadcast read)
                            asm volatile("ld.acquire.gpu.u32 %0, [%1];"
                                         : "=r"(v) : "l"(c));
                        } while (v < (unsigned)t);
                    }
                    pk = __ldcg((const uint4*)(pin + (e & 0xFFFF) * QN) + lane);
                }
                *(uint4*)(sh + A_OFF + r * A_ROW + lane * 16) = pk;
            }
            __syncthreads();

            // ---- prefetch t+1 row list in the MMA shadow (once per step)
            if (pf) {
                for (int i = tid; i < bktn.y; i += NTHREADS)
                    sbn[i] = g_order[(t + 1) * BN + bktn.x + i];
                pf = false;
            }

            // ---- tile 0 (rows o..o+15)
            compute_tile(pa, browB, min(mg, 16), sbc + o, pout, n, qp, sc);
            // ---- tile 1 (rows o+16..o+31), rare straggler path
            if (mg > 16)
                compute_tile(pa, browB + 16 * (A_ROW / 4), mg - 16,
                             sbc + o + 16, pout, n, qp, sc);

            __syncthreads();   // epilogue stores + sbn prefetch complete
            o += 32;
        }
        if (pf) {   // empty bucket: still prefetch next list
            for (int i = tid; i < bktn.y; i += NTHREADS)
                sbn[i] = g_order[(t + 1) * BN + bktn.x + i];
            __syncthreads();
        }

        // ---- publish: this CTA finished step t (own line, no atomics)
        if (t + 1 < TN && tid == 0)
            asm volatile("st.release.gpu.global.u32 [%0], %1;"
                         :: "l"(&g_done[s * 32]), "r"((unsigned)(t + 1)) : "memory");
        bkt = bktn;
    }
}

// ---------------------------------------------------------------------------
// out[b] = log( sum_q alpha_bf16[b][q] * exp(final[q]) ) + 128*ln(256)
__global__ void final_kernel(const float* __restrict__ finalw, float* __restrict__ out) {
    int b = blockIdx.x * 8 + (threadIdx.x >> 5);
    int lane = threadIdx.x & 31;
    const __nv_bfloat16* ar = (const __nv_bfloat16*)g_alpha[0] + b * QN;  // T even
    float sum = 0.0f;
    #pragma unroll
    for (int i = 0; i < 8; i++) {
        int q = lane + 32 * i;
        sum += __bfloat162float(ar[q]) * __expf(finalw[q]);
    }
    #pragma unroll
    for (int o = 16; o > 0; o >>= 1) sum += __shfl_xor_sync(0xFFFFFFFFu, sum, o);
    if (lane == 0)
        out[b] = logf(sum) + (float)(128.0 * 5.545177444479562);  // T * ln(256)
}

// ---------------------------------------------------------------------------
extern "C" void kernel_launch(void* const* d_in, const int* in_sizes, int n_in,
                              void* d_out, int out_size) {
    const float* A      = (const float*)d_in[0];  // [Q,S,Q] fp32
    const float* init   = (const float*)d_in[1];  // [Q]
    const float* finalw = (const float*)d_in[2];  // [Q]
    const int*   xs     = (const int*)d_in[3];    // [B,T] int32
    float* out = (float*)d_out;                   // [B]

    cudaFuncSetAttribute(fsa_kernel,
                         cudaFuncAttributeMaxDynamicSharedMemorySize, SH_BYTES);

    exp_kernel<<<(SN * QN * QN / 2) / 256, 256>>>(A);
    init_kernel<<<BN, QN>>>(init);
    bucket_kernel<<<TN, 256>>>(xs);
    fsa_kernel<<<SN, NTHREADS, SH_BYTES>>>();
    final_kernel<<<BN / 8, 256>>>(finalw, out);
}